// round 16
// baseline (speedup 1.0000x reference)
#include <cuda_runtime.h>
#include <cuda_fp16.h>
#include <cstdint>

// ---------------- problem dims ----------------
static constexpr int DK = 4096;   // inner (d)
static constexpr int DN = 4096;   // out features (o)
static constexpr int DM = 8192;   // rows (b*s)

// ---------------- GEMM tiling (champion config) ----------------
static constexpr int BM = 128;
static constexpr int BN = 128;
static constexpr int BK = 64;            // 64 f16 = 128B rows (SW128 friendly)
static constexpr int STAGES = 3;
static constexpr int KCHUNKS = DK / BK;  // 64
static constexpr int NTHREADS = 256;     // 8 warps: 2 (m) x 4 (n), warp tile 64x32

static constexpr int A_STAGE_BYTES = BM * BK * 2;  // 16384
static constexpr int B_STAGE_BYTES = BN * BK * 2;  // 16384
static constexpr int STAGE_BYTES = A_STAGE_BYTES + B_STAGE_BYTES;  // 32768
static constexpr int SMEM_TOTAL = STAGES * STAGE_BYTES;            // 98304 -> 2 CTAs/SM

// ---------------- scratch (device globals: no allocs allowed) ----------------
__device__ __align__(256) __half g_w[(size_t)DN * DK];  // 32 MB ternary W (fp16 exact)
__device__ __align__(256) __half g_x[(size_t)DM * DK];  // 64 MB x in fp16

// ---------------- PTX helpers (base sm_103 ISA only) ----------
__device__ __forceinline__ uint32_t smem_u32(const void* p) {
    uint32_t a;
    asm("{ .reg .u64 t; cvta.to.shared.u64 t, %1; cvt.u32.u64 %0, t; }"
        : "=r"(a) : "l"(p));
    return a;
}

#define SWZ128(o) ((o) ^ (((o) >> 3) & 0x70))

#define CP_ASYNC16(smem_addr, gptr) \
    asm volatile("cp.async.cg.shared.global [%0], [%1], 16;" \
        :: "r"(smem_addr), "l"(gptr) : "memory")
#define CP_ASYNC_COMMIT() asm volatile("cp.async.commit_group;" ::: "memory")
#define CP_ASYNC_WAIT(n)  asm volatile("cp.async.wait_group %0;" :: "n"(n) : "memory")

#define LDMATRIX_X4(r0, r1, r2, r3, addr) \
    asm volatile("ldmatrix.sync.aligned.m8n8.x4.shared.b16 {%0,%1,%2,%3}, [%4];" \
        : "=r"(r0), "=r"(r1), "=r"(r2), "=r"(r3) : "r"(addr))

__device__ __forceinline__ void mma_16816(float* c, uint32_t a0, uint32_t a1,
                                          uint32_t a2, uint32_t a3,
                                          uint32_t b0, uint32_t b1) {
    asm volatile(
        "mma.sync.aligned.m16n8k16.row.col.f32.f16.f16.f32 "
        "{%0,%1,%2,%3}, {%4,%5,%6,%7}, {%8,%9}, {%0,%1,%2,%3};"
        : "+f"(c[0]), "+f"(c[1]), "+f"(c[2]), "+f"(c[3])
        : "r"(a0), "r"(a1), "r"(a2), "r"(a3), "r"(b0), "r"(b1));
}

// streaming 8B store (evict-first: output is never re-read)
__device__ __forceinline__ void stg_cs_f2(float* p, float2 v) {
    asm volatile("st.global.cs.v2.f32 [%0], {%1, %2};" :: "l"(p), "f"(v.x), "f"(v.y) : "memory");
}

// ---------------- preprocess kernels (separate; evict-first input loads) ------
__global__ void __launch_bounds__(256) prep_w_kernel(const float* __restrict__ wp,
                                                     const float* __restrict__ wn) {
    size_t i = (size_t)blockIdx.x * 256 + threadIdx.x;
    float4 p = __ldcs(reinterpret_cast<const float4*>(wp) + i);
    float4 n = __ldcs(reinterpret_cast<const float4*>(wn) + i);
    float v0 = (float)((int)(p.x > 0.f) - (int)(n.x <= 0.f));
    float v1 = (float)((int)(p.y > 0.f) - (int)(n.y <= 0.f));
    float v2 = (float)((int)(p.z > 0.f) - (int)(n.z <= 0.f));
    float v3 = (float)((int)(p.w > 0.f) - (int)(n.w <= 0.f));
    __half2 h01 = __floats2half2_rn(v0, v1);
    __half2 h23 = __floats2half2_rn(v2, v3);
    uint2 o;
    o.x = *reinterpret_cast<uint32_t*>(&h01);
    o.y = *reinterpret_cast<uint32_t*>(&h23);
    reinterpret_cast<uint2*>(g_w)[i] = o;
}

__global__ void __launch_bounds__(256) prep_x_kernel(const float* __restrict__ x) {
    size_t i = (size_t)blockIdx.x * 256 + threadIdx.x;
    float4 v = __ldcs(reinterpret_cast<const float4*>(x) + i);
    __half2 h01 = __floats2half2_rn(v.x, v.y);
    __half2 h23 = __floats2half2_rn(v.z, v.w);
    uint2 o;
    o.x = *reinterpret_cast<uint32_t*>(&h01);
    o.y = *reinterpret_cast<uint32_t*>(&h23);
    reinterpret_cast<uint2*>(g_x)[i] = o;
}

// ---------------- main GEMM: y = x @ W^T (fp16 in, fp32 accum, mma.sync) -------
// CTA 128x128x64, 8 warps (2x4), warp tile 64x32, 3-stage cp.async pipeline,
// ONE __syncthreads per chunk; compute THEN prefetch; chunk loop unrolled 3x so
// all stage indices/bases are compile-time constants; running global pointers.
__global__ void __launch_bounds__(NTHREADS, 2) plinear_gemm_kernel(float* __restrict__ out) {
    extern __shared__ char smem[];
    const uint32_t sb = smem_u32(smem);
    const int tid = threadIdx.x;
    const int wid = tid >> 5;
    const int lid = tid & 31;
    const int warp_m = wid >> 2;       // 0..1  (64 rows each)
    const int warp_n = wid & 3;        // 0..3  (32 cols each)
    const int m_base = blockIdx.y * BM;
    const int n_base = blockIdx.x * BN;

    // ---- per-thread cp.async map: per chunk, A = 1024 x 16B units, B = 1024 ----
    uint32_t sA_off[4], sB_off[4];
    const __half* gA[4];   // running pointers, advanced BK per chunk
    const __half* gB[4];
#pragma unroll
    for (int j = 0; j < 4; ++j) {
        int u = tid + j * 256;            // unit 0..1023
        int row = u >> 3;                 // 128 rows x 8 (16B cols)
        int col = u & 7;
        uint32_t off = SWZ128((uint32_t)(row * 128 + col * 16));
        sA_off[j] = off;
        sB_off[j] = A_STAGE_BYTES + off;
        gA[j] = g_x + (size_t)(m_base + row) * DK + col * 8;
        gB[j] = g_w + (size_t)(n_base + row) * DK + col * 8;
    }

    // ---- ldmatrix lane maps (validated) ----
    const int a_row_in_tile = (lid & 7) + ((lid >> 3) & 1) * 8;
    const int a_khalf16B = (lid >> 4) & 1;
    const int b_row_in_pair = ((lid >> 4) & 1) * 8 + (lid & 7);
    const int b_khalf16B = (lid >> 3) & 1;

    // per-warp swizzled smem base offsets (stage-relative), constant across loop
    const int a_row0 = warp_m * 64 + a_row_in_tile;
    const int b_row0 = warp_n * 32 + b_row_in_pair;

    float acc[4][4][4];   // [mtile][ntile][frag] : warp tile 64x32
#pragma unroll
    for (int mt = 0; mt < 4; ++mt)
#pragma unroll
        for (int nt = 0; nt < 4; ++nt)
#pragma unroll
            for (int q = 0; q < 4; ++q) acc[mt][nt][q] = 0.f;

    // ---- pipeline prologue: fill stages 0,1 with chunks 0,1 ----
#pragma unroll
    for (int s = 0; s < STAGES - 1; ++s) {
        uint32_t st = sb + s * STAGE_BYTES;
#pragma unroll
        for (int j = 0; j < 4; ++j) {
            CP_ASYNC16(st + sA_off[j], gA[j] + s * BK);
            CP_ASYNC16(st + sB_off[j], gB[j] + s * BK);
        }
        CP_ASYNC_COMMIT();
    }

    // one chunk body; cs = compute stage (compile-time), prefetches into same
    // stage slot cs (which equals (i+STAGES)%STAGES... i%3 == (i+3)%3) wait —
    // prefetch target stage is (i+2)%3; with cs = i%3 the target is (cs+2)%3.
    auto chunk = [&](int cs_stage, int pf_stage, bool do_pf) {
        CP_ASYNC_WAIT(STAGES - 2);
        __syncthreads();   // all warps done computing previous chunk

        const uint32_t sA = sb + cs_stage * STAGE_BYTES;
        const uint32_t sB = sA + A_STAGE_BYTES;

#pragma unroll
        for (int ks = 0; ks < 4; ++ks) {      // 4 x k16 per BK=64 chunk
            uint32_t a[4][4];
#pragma unroll
            for (int mt = 0; mt < 4; ++mt) {
                int row = a_row0 + mt * 16;
                uint32_t off = (uint32_t)(row * 128 + ks * 32 + a_khalf16B * 16);
                LDMATRIX_X4(a[mt][0], a[mt][1], a[mt][2], a[mt][3], sA + SWZ128(off));
            }
            uint32_t b[2][4];
#pragma unroll
            for (int np = 0; np < 2; ++np) {  // each covers 16 cols (2 n-tiles)
                int row = b_row0 + np * 16;
                uint32_t off = (uint32_t)(row * 128 + ks * 32 + b_khalf16B * 16);
                LDMATRIX_X4(b[np][0], b[np][1], b[np][2], b[np][3], sB + SWZ128(off));
            }
#pragma unroll
            for (int mt = 0; mt < 4; ++mt)
#pragma unroll
                for (int nt = 0; nt < 4; ++nt) {
                    int np = nt >> 1, sel = (nt & 1) * 2;
                    mma_16816(acc[mt][nt], a[mt][0], a[mt][1], a[mt][2], a[mt][3],
                              b[np][sel], b[np][sel + 1]);
                }
        }

        // prefetch chunk i+2 into stage pf_stage from running ptr + 2*BK
        if (do_pf) {
            uint32_t st = sb + pf_stage * STAGE_BYTES;
#pragma unroll
            for (int j = 0; j < 4; ++j) {
                CP_ASYNC16(st + sA_off[j], gA[j] + 2 * BK);
                CP_ASYNC16(st + sB_off[j], gB[j] + 2 * BK);
            }
        }
        CP_ASYNC_COMMIT();

        // advance running pointers by one chunk
#pragma unroll
        for (int j = 0; j < 4; ++j) { gA[j] += BK; gB[j] += BK; }
    };

    // ---- main loop: 60 chunks unrolled by 3 (compile-time stages), 4-chunk tail
#pragma unroll 1
    for (int i = 0; i < KCHUNKS - 4; i += 3) {
        chunk(0, 2, true);
        chunk(1, 0, true);
        chunk(2, 1, true);
    }
    // chunks 60..63: stages 0,1,2,0 ; prefetch valid for chunks 60,61 only
    chunk(0, 2, true);    // i=60, pf=62
    chunk(1, 0, true);    // i=61, pf=63
    chunk(2, 1, false);   // i=62
    chunk(0, 2, false);   // i=63

    // ---- epilogue: streaming fp32 stores (output never re-read) ----
    const int gq = lid >> 2;        // row offset within 8
    const int tq = lid & 3;         // col pair
#pragma unroll
    for (int mt = 0; mt < 4; ++mt) {
#pragma unroll
        for (int nt = 0; nt < 4; ++nt) {
            int m0 = m_base + warp_m * 64 + mt * 16 + gq;
            int n0 = n_base + warp_n * 32 + nt * 8 + tq * 2;
            stg_cs_f2(out + (size_t)m0 * DN + n0,
                      make_float2(acc[mt][nt][0], acc[mt][nt][1]));
            stg_cs_f2(out + (size_t)(m0 + 8) * DN + n0,
                      make_float2(acc[mt][nt][2], acc[mt][nt][3]));
        }
    }
}

// ---------------- launch ----------------
extern "C" void kernel_launch(void* const* d_in, const int* in_sizes, int n_in,
                              void* d_out, int out_size) {
    (void)in_sizes; (void)n_in; (void)out_size;
    const float* x  = (const float*)d_in[0];   // [8,1024,4096] f32
    const float* wp = (const float*)d_in[1];   // [4096,4096] f32
    const float* wn = (const float*)d_in[2];   // [4096,4096] f32
    float* out = (float*)d_out;                // [8,1024,4096] f32

    cudaFuncSetAttribute(plinear_gemm_kernel,
                         cudaFuncAttributeMaxDynamicSharedMemorySize, SMEM_TOTAL);

    prep_w_kernel<<<(DN * DK / 4) / 256, 256>>>(wp, wn);
    prep_x_kernel<<<(int)(((size_t)DM * DK / 4) / 256), 256>>>(x);

    dim3 grid(DN / BN, DM / BM);  // (32, 64)
    plinear_gemm_kernel<<<grid, NTHREADS, SMEM_TOTAL>>>(out);
}

// round 17
// speedup vs baseline: 1.0671x; 1.0671x over previous
#include <cuda_runtime.h>
#include <cuda_fp16.h>
#include <cstdint>

// ---------------- problem dims ----------------
static constexpr int DK = 4096;   // inner (d)
static constexpr int DN = 4096;   // out features (o)
static constexpr int DM = 8192;   // rows (b*s)

// ---------------- GEMM tiling (champion r15 config) ----------------
static constexpr int BM = 128;
static constexpr int BN = 128;
static constexpr int BK = 64;            // 64 f16 = 128B rows (SW128 friendly)
static constexpr int STAGES = 3;
static constexpr int KCHUNKS = DK / BK;  // 64
static constexpr int NTHREADS = 256;     // 8 warps: 2 (m) x 4 (n), warp tile 64x32

static constexpr int A_STAGE_BYTES = BM * BK * 2;  // 16384
static constexpr int B_STAGE_BYTES = BN * BK * 2;  // 16384
static constexpr int STAGE_BYTES = A_STAGE_BYTES + B_STAGE_BYTES;  // 32768
static constexpr int SMEM_TOTAL = STAGES * STAGE_BYTES;            // 98304 -> 2 CTAs/SM

// ---------------- scratch (device globals: no allocs allowed) ----------------
__device__ __align__(256) __half g_w[(size_t)DN * DK];  // 32 MB ternary W (fp16 exact)
__device__ __align__(256) __half g_x[(size_t)DM * DK];  // 64 MB x in fp16

// ---------------- PTX helpers (base sm_103 ISA only) ----------
__device__ __forceinline__ uint32_t smem_u32(const void* p) {
    uint32_t a;
    asm("{ .reg .u64 t; cvta.to.shared.u64 t, %1; cvt.u32.u64 %0, t; }"
        : "=r"(a) : "l"(p));
    return a;
}

#define SWZ128(o) ((o) ^ (((o) >> 3) & 0x70))

#define CP_ASYNC16(smem_addr, gptr) \
    asm volatile("cp.async.cg.shared.global [%0], [%1], 16;" \
        :: "r"(smem_addr), "l"(gptr) : "memory")
#define CP_ASYNC_COMMIT() asm volatile("cp.async.commit_group;" ::: "memory")
#define CP_ASYNC_WAIT(n)  asm volatile("cp.async.wait_group %0;" :: "n"(n) : "memory")

#define LDMATRIX_X4(r0, r1, r2, r3, addr) \
    asm volatile("ldmatrix.sync.aligned.m8n8.x4.shared.b16 {%0,%1,%2,%3}, [%4];" \
        : "=r"(r0), "=r"(r1), "=r"(r2), "=r"(r3) : "r"(addr))

__device__ __forceinline__ void mma_16816(float* c, uint32_t a0, uint32_t a1,
                                          uint32_t a2, uint32_t a3,
                                          uint32_t b0, uint32_t b1) {
    asm volatile(
        "mma.sync.aligned.m16n8k16.row.col.f32.f16.f16.f32 "
        "{%0,%1,%2,%3}, {%4,%5,%6,%7}, {%8,%9}, {%0,%1,%2,%3};"
        : "+f"(c[0]), "+f"(c[1]), "+f"(c[2]), "+f"(c[3])
        : "r"(a0), "r"(a1), "r"(a2), "r"(a3), "r"(b0), "r"(b1));
}

// streaming 8B store (evict-first: output is never re-read)
__device__ __forceinline__ void stg_cs_f2(float* p, float2 v) {
    asm volatile("st.global.cs.v2.f32 [%0], {%1, %2};" :: "l"(p), "f"(v.x), "f"(v.y) : "memory");
}

// ---------------- preprocess kernels (separate; evict-first input loads) ------
__global__ void __launch_bounds__(256) prep_w_kernel(const float* __restrict__ wp,
                                                     const float* __restrict__ wn) {
    size_t i = (size_t)blockIdx.x * 256 + threadIdx.x;
    float4 p = __ldcs(reinterpret_cast<const float4*>(wp) + i);
    float4 n = __ldcs(reinterpret_cast<const float4*>(wn) + i);
    float v0 = (float)((int)(p.x > 0.f) - (int)(n.x <= 0.f));
    float v1 = (float)((int)(p.y > 0.f) - (int)(n.y <= 0.f));
    float v2 = (float)((int)(p.z > 0.f) - (int)(n.z <= 0.f));
    float v3 = (float)((int)(p.w > 0.f) - (int)(n.w <= 0.f));
    __half2 h01 = __floats2half2_rn(v0, v1);
    __half2 h23 = __floats2half2_rn(v2, v3);
    uint2 o;
    o.x = *reinterpret_cast<uint32_t*>(&h01);
    o.y = *reinterpret_cast<uint32_t*>(&h23);
    reinterpret_cast<uint2*>(g_w)[i] = o;
}

__global__ void __launch_bounds__(256) prep_x_kernel(const float* __restrict__ x) {
    size_t i = (size_t)blockIdx.x * 256 + threadIdx.x;
    float4 v = __ldcs(reinterpret_cast<const float4*>(x) + i);
    __half2 h01 = __floats2half2_rn(v.x, v.y);
    __half2 h23 = __floats2half2_rn(v.z, v.w);
    uint2 o;
    o.x = *reinterpret_cast<uint32_t*>(&h01);
    o.y = *reinterpret_cast<uint32_t*>(&h23);
    reinterpret_cast<uint2*>(g_x)[i] = o;
}

// ---------------- main GEMM: y = x @ W^T (fp16 in, fp32 accum, mma.sync) -------
// CTA 128x128x64, 8 warps (2x4), warp tile 64x32, 3-stage cp.async pipeline,
// ONE __syncthreads per chunk; compute THEN prefetch (champion ordering).
__global__ void __launch_bounds__(NTHREADS, 2) plinear_gemm_kernel(float* __restrict__ out) {
    extern __shared__ char smem[];
    const uint32_t sb = smem_u32(smem);
    const int tid = threadIdx.x;
    const int wid = tid >> 5;
    const int lid = tid & 31;
    const int warp_m = wid >> 2;       // 0..1  (64 rows each)
    const int warp_n = wid & 3;        // 0..3  (32 cols each)
    const int m_base = blockIdx.y * BM;
    const int n_base = blockIdx.x * BN;

    // ---- per-thread cp.async map: per chunk, A = 1024 x 16B units, B = 1024 ----
    uint32_t sA_off[4], sB_off[4];
    const __half* gA[4];
    const __half* gB[4];
#pragma unroll
    for (int j = 0; j < 4; ++j) {
        int u = tid + j * 256;            // unit 0..1023
        int row = u >> 3;                 // 128 rows x 8 (16B cols)
        int col = u & 7;
        uint32_t off = SWZ128((uint32_t)(row * 128 + col * 16));
        sA_off[j] = off;
        sB_off[j] = A_STAGE_BYTES + off;
        gA[j] = g_x + (size_t)(m_base + row) * DK + col * 8;
        gB[j] = g_w + (size_t)(n_base + row) * DK + col * 8;
    }

    // ---- ldmatrix lane maps (validated) ----
    const int a_row_in_tile = (lid & 7) + ((lid >> 3) & 1) * 8;
    const int a_khalf16B = (lid >> 4) & 1;
    const int b_row_in_pair = ((lid >> 4) & 1) * 8 + (lid & 7);
    const int b_khalf16B = (lid >> 3) & 1;

    float acc[4][4][4];   // [mtile][ntile][frag] : warp tile 64x32
#pragma unroll
    for (int mt = 0; mt < 4; ++mt)
#pragma unroll
        for (int nt = 0; nt < 4; ++nt)
#pragma unroll
            for (int q = 0; q < 4; ++q) acc[mt][nt][q] = 0.f;

    // ---- pipeline prologue: fill STAGES-1 stages (chunks 0,1) ----
#pragma unroll
    for (int s = 0; s < STAGES - 1; ++s) {
        uint32_t st = sb + s * STAGE_BYTES;
#pragma unroll
        for (int j = 0; j < 4; ++j) {
            CP_ASYNC16(st + sA_off[j], gA[j] + s * BK);
            CP_ASYNC16(st + sB_off[j], gB[j] + s * BK);
        }
        CP_ASYNC_COMMIT();
    }

    // ---- main loop: wait / sync / compute(i) / prefetch(i+2) ----
    for (int i = 0; i < KCHUNKS; ++i) {
        CP_ASYNC_WAIT(STAGES - 2);
        __syncthreads();   // all warps done computing chunk i-1 => stage (i+2)%3 free

        const uint32_t stage = sb + (i % STAGES) * STAGE_BYTES;
        const uint32_t sA = stage;
        const uint32_t sB = stage + A_STAGE_BYTES;

#pragma unroll
        for (int ks = 0; ks < 4; ++ks) {      // 4 x k16 per BK=64 chunk
            uint32_t a[4][4];
#pragma unroll
            for (int mt = 0; mt < 4; ++mt) {
                int row = warp_m * 64 + mt * 16 + a_row_in_tile;
                uint32_t off = (uint32_t)(row * 128 + ks * 32 + a_khalf16B * 16);
                LDMATRIX_X4(a[mt][0], a[mt][1], a[mt][2], a[mt][3], sA + SWZ128(off));
            }
            uint32_t b[2][4];
#pragma unroll
            for (int np = 0; np < 2; ++np) {  // each covers 16 cols (2 n-tiles)
                int row = warp_n * 32 + np * 16 + b_row_in_pair;
                uint32_t off = (uint32_t)(row * 128 + ks * 32 + b_khalf16B * 16);
                LDMATRIX_X4(b[np][0], b[np][1], b[np][2], b[np][3], sB + SWZ128(off));
            }
#pragma unroll
            for (int mt = 0; mt < 4; ++mt)
#pragma unroll
                for (int nt = 0; nt < 4; ++nt) {
                    int np = nt >> 1, sel = (nt & 1) * 2;
                    mma_16816(acc[mt][nt], a[mt][0], a[mt][1], a[mt][2], a[mt][3],
                              b[np][sel], b[np][sel + 1]);
                }
        }

        // prefetch chunk i+2 into stage (i+2)%3 (freed by the sync above)
        int pf = i + STAGES - 1;
        if (pf < KCHUNKS) {
            uint32_t st = sb + (pf % STAGES) * STAGE_BYTES;
#pragma unroll
            for (int j = 0; j < 4; ++j) {
                CP_ASYNC16(st + sA_off[j], gA[j] + pf * BK);
                CP_ASYNC16(st + sB_off[j], gB[j] + pf * BK);
            }
        }
        CP_ASYNC_COMMIT();
    }

    // ---- epilogue: streaming fp32 stores (output never re-read) ----
    const int gq = lid >> 2;        // row offset within 8
    const int tq = lid & 3;         // col pair
#pragma unroll
    for (int mt = 0; mt < 4; ++mt) {
#pragma unroll
        for (int nt = 0; nt < 4; ++nt) {
            int m0 = m_base + warp_m * 64 + mt * 16 + gq;
            int n0 = n_base + warp_n * 32 + nt * 8 + tq * 2;
            stg_cs_f2(out + (size_t)m0 * DN + n0,
                      make_float2(acc[mt][nt][0], acc[mt][nt][1]));
            stg_cs_f2(out + (size_t)(m0 + 8) * DN + n0,
                      make_float2(acc[mt][nt][2], acc[mt][nt][3]));
        }
    }
}

// ---------------- launch ----------------
extern "C" void kernel_launch(void* const* d_in, const int* in_sizes, int n_in,
                              void* d_out, int out_size) {
    (void)in_sizes; (void)n_in; (void)out_size;
    const float* x  = (const float*)d_in[0];   // [8,1024,4096] f32
    const float* wp = (const float*)d_in[1];   // [4096,4096] f32
    const float* wn = (const float*)d_in[2];   // [4096,4096] f32
    float* out = (float*)d_out;                // [8,1024,4096] f32

    cudaFuncSetAttribute(plinear_gemm_kernel,
                         cudaFuncAttributeMaxDynamicSharedMemorySize, SMEM_TOTAL);

    prep_w_kernel<<<(DN * DK / 4) / 256, 256>>>(wp, wn);
    prep_x_kernel<<<(int)(((size_t)DM * DK / 4) / 256), 256>>>(x);

    dim3 grid(DN / BN, DM / BM);  // (32, 64)
    plinear_gemm_kernel<<<grid, NTHREADS, SMEM_TOTAL>>>(out);
}